// round 14
// baseline (speedup 1.0000x reference)
#include <cuda_runtime.h>
#include <cuda_bf16.h>
#include <cstdint>

#define CC   512
#define NN   4096
#define BB   2
#define GRPS 32
#define CPG  16
#define EPSF 1e-5f
#define BKE  64            // k elements per pipeline stage
#define RSTR 72            // smem row stride in bf16 (64 data + 8 pad), 144B = 16B-aligned
#define GC_SMEM (2 * 2 * 128 * RSTR * 2)   // 73728 bytes (2 stages x A+B tiles)

typedef __nv_bfloat16  bf16;
typedef __nv_bfloat162 bf162;

// ---------------- scratch (device globals: allocation-free) ----------------
__device__ bf16  g_hn[BB * NN * CC];            // GN output, token-major [b][n][c]
__device__ bf16  g_q [BB * NN * CC];            // pre-scaled q [b][n][c]
__device__ bf16  g_k [BB * NN * CC];            // [b][n][c]
__device__ bf16  g_v [BB * CC * NN];            // [b][c][n]
__device__ bf16  g_P [BB * (size_t)NN * NN];    // unnormalized exp scores bf16 [b][q][k]
__device__ float g_rsum[BB * NN];               // per-row exp sums
__device__ float g_gstat[BB * GRPS * 2];        // groupnorm partial sums (s, s2)
__device__ bf16  g_o [BB * NN * CC];            // attn out [b][q][c]
__device__ bf16  g_wq[CC * CC], g_wk[CC * CC], g_wv[CC * CC], g_wp[CC * CC];

// ---------------- prep: weight fp32->bf16, zero accs, GN partial stats -------
__global__ __launch_bounds__(256)
void prep_kernel(const float* __restrict__ qw, const float* __restrict__ kw,
                 const float* __restrict__ vw, const float* __restrict__ pw,
                 const float* __restrict__ x) {
    if (blockIdx.x < 1024) {
        const int i = blockIdx.x * 256 + threadIdx.x;
        if (i < BB * NN) g_rsum[i] = 0.f;
        if (i < BB * GRPS * 2) g_gstat[i] = 0.f;
        const int which = i >> 16, j = i & 65535;
        const float* src = which == 0 ? qw : which == 1 ? kw : which == 2 ? vw : pw;
        bf16* dst = which == 0 ? g_wq : which == 1 ? g_wk : which == 2 ? g_wv : g_wp;
        float4 v = ((const float4*)src)[j];
        bf162* d2 = (bf162*)(dst + (size_t)j * 4);
        d2[0] = __floats2bfloat162_rn(v.x, v.y);
        d2[1] = __floats2bfloat162_rn(v.z, v.w);
        return;
    }
    const int idx = blockIdx.x - 1024;           // 0..255
    const int bg = idx >> 2;                     // 0..63
    const int b  = bg / GRPS, g = bg % GRPS;
    const int qy = idx & 3;
    const size_t base = ((size_t)b * CC + (size_t)g * CPG + qy * 4) * NN;
    const float4* __restrict__ xp4 = (const float4*)(x + base);
    const int t = threadIdx.x;
    float s = 0.f, s2 = 0.f;
    #pragma unroll 4
    for (int i = t; i < 4096; i += 256) {
        float4 v = xp4[i];
        s  += v.x + v.y + v.z + v.w;
        s2 += v.x * v.x + v.y * v.y + v.z * v.z + v.w * v.w;
    }
    #pragma unroll
    for (int o = 16; o; o >>= 1) {
        s  += __shfl_xor_sync(~0u, s, o);
        s2 += __shfl_xor_sync(~0u, s2, o);
    }
    __shared__ float r1[8], r2[8];
    const int wid = t >> 5, lid = t & 31;
    if (lid == 0) { r1[wid] = s; r2[wid] = s2; }
    __syncthreads();
    if (t == 0) {
        s = r1[0] + r1[1] + r1[2] + r1[3] + r1[4] + r1[5] + r1[6] + r1[7];
        s2 = r2[0] + r2[1] + r2[2] + r2[3] + r2[4] + r2[5] + r2[6] + r2[7];
        atomicAdd(&g_gstat[bg * 2], s);
        atomicAdd(&g_gstat[bg * 2 + 1], s2);
    }
}

// ---------------- GroupNorm pass 2: apply + transpose to bf16 [n][c] ---------
__global__ __launch_bounds__(1024)
void gn_apply(const float* __restrict__ x,
              const float* __restrict__ gw, const float* __restrict__ gb) {
    const int bg = blockIdx.x >> 2;
    const int b  = bg / GRPS, g = bg % GRPS;
    const int n  = (blockIdx.x & 3) * 1024 + threadIdx.x;
    __shared__ float stat[2];
    if (threadIdx.x < 2) stat[threadIdx.x] = g_gstat[bg * 2 + threadIdx.x];
    __syncthreads();
    const float invN = 1.0f / (float)(CPG * NN);
    const float mean = stat[0] * invN;
    const float var  = stat[1] * invN - mean * mean;
    const float istd = rsqrtf(var + EPSF);

    const float* __restrict__ xs = x + ((size_t)b * CC + (size_t)g * CPG) * NN;
    bf16* __restrict__ dst = g_hn + (size_t)b * NN * CC + g * CPG;
    alignas(16) bf162 o[8];
    #pragma unroll
    for (int ci = 0; ci < CPG; ci += 2) {
        const float sc0 = gw[g * CPG + ci] * istd;
        const float sh0 = gb[g * CPG + ci] - mean * sc0;
        const float sc1 = gw[g * CPG + ci + 1] * istd;
        const float sh1 = gb[g * CPG + ci + 1] - mean * sc1;
        float v0 = xs[(size_t)ci * NN + n] * sc0 + sh0;
        float v1 = xs[(size_t)(ci + 1) * NN + n] * sc1 + sh1;
        o[ci >> 1] = __floats2bfloat162_rn(v0, v1);
    }
    *(uint4*)&dst[(size_t)n * CC]     = *(uint4*)&o[0];
    *(uint4*)&dst[(size_t)n * CC + 8] = *(uint4*)&o[4];
}

// ============================================================================
// bf16 ldmatrix/mma GEMM core — 2-stage, BK=64, block 128x128, warp 64x32
// (exact round-9 measured-best version: two barriers per iteration)
// ============================================================================
__device__ __forceinline__ void gemm_core(
    const bf16* __restrict__ A, int lda,
    const bf16* __restrict__ B, int ldb,
    int m0, int n0, int K, float (&acc)[4][4][4])
{
    extern __shared__ bf16 dsm[];
    bf16* As[2] = { dsm,                  dsm + 2 * 128 * RSTR };
    bf16* Bs[2] = { dsm + 128 * RSTR,     dsm + 3 * 128 * RSTR };
    const int t = threadIdx.x, lane = t & 31, w = t >> 5;
    const int wm = (w & 1) * 64, wn = (w >> 1) * 32;
    const int grp = lane >> 3, lr = lane & 7;

    uint32_t dA[2][4], dB[2][4], asb[2], bsb[2];
    const bf16* gA[4]; const bf16* gB[4];
    #pragma unroll
    for (int l = 0; l < 4; l++) {
        const int i = t + l * 256;
        const int row = i >> 3, c8 = (i & 7) * 8;
        gA[l] = A + (size_t)(m0 + row) * lda + c8;
        gB[l] = B + (size_t)(n0 + row) * ldb + c8;
        #pragma unroll
        for (int s = 0; s < 2; s++) {
            dA[s][l] = (uint32_t)__cvta_generic_to_shared(&As[s][row * RSTR + c8]);
            dB[s][l] = (uint32_t)__cvta_generic_to_shared(&Bs[s][row * RSTR + c8]);
        }
    }
    #pragma unroll
    for (int s = 0; s < 2; s++) {
        asb[s] = (uint32_t)__cvta_generic_to_shared(As[s]);
        bsb[s] = (uint32_t)__cvta_generic_to_shared(Bs[s]);
    }
    int aoff[4], boff[2];
    #pragma unroll
    for (int mt = 0; mt < 4; mt++)
        aoff[mt] = ((wm + mt * 16 + (grp & 1) * 8 + lr) * RSTR + (grp >> 1) * 8) * 2;
    #pragma unroll
    for (int bt = 0; bt < 2; bt++)
        boff[bt] = ((wn + bt * 16 + (grp >> 1) * 8 + lr) * RSTR + (grp & 1) * 8) * 2;

    const int iters = K / BKE;

    auto stage = [&](int s, int kc) {
        #pragma unroll
        for (int l = 0; l < 4; l++) {
            asm volatile("cp.async.cg.shared.global [%0], [%1], 16;\n" :: "r"(dA[s][l]), "l"(gA[l] + kc) : "memory");
            asm volatile("cp.async.cg.shared.global [%0], [%1], 16;\n" :: "r"(dB[s][l]), "l"(gB[l] + kc) : "memory");
        }
        asm volatile("cp.async.commit_group;\n" ::: "memory");
    };
    auto compute = [&](int s) {
        #pragma unroll
        for (int kk = 0; kk < 4; kk++) {
            uint32_t af[4][4], bfr[2][4];
            #pragma unroll
            for (int mt = 0; mt < 4; mt++) {
                asm volatile("ldmatrix.sync.aligned.m8n8.x4.shared.b16 {%0,%1,%2,%3}, [%4];\n"
                             : "=r"(af[mt][0]), "=r"(af[mt][1]), "=r"(af[mt][2]), "=r"(af[mt][3])
                             : "r"(asb[s] + aoff[mt] + kk * 32));
            }
            #pragma unroll
            for (int bt = 0; bt < 2; bt++) {
                asm volatile("ldmatrix.sync.aligned.m8n8.x4.shared.b16 {%0,%1,%2,%3}, [%4];\n"
                             : "=r"(bfr[bt][0]), "=r"(bfr[bt][1]), "=r"(bfr[bt][2]), "=r"(bfr[bt][3])
                             : "r"(bsb[s] + boff[bt] + kk * 32));
            }
            #pragma unroll
            for (int mt = 0; mt < 4; mt++)
                #pragma unroll
                for (int nt = 0; nt < 4; nt++) {
                    asm volatile(
                        "mma.sync.aligned.m16n8k16.row.col.f32.bf16.bf16.f32 "
                        "{%0,%1,%2,%3},{%4,%5,%6,%7},{%8,%9},{%0,%1,%2,%3};\n"
                        : "+f"(acc[mt][nt][0]), "+f"(acc[mt][nt][1]),
                          "+f"(acc[mt][nt][2]), "+f"(acc[mt][nt][3])
                        : "r"(af[mt][0]), "r"(af[mt][1]), "r"(af[mt][2]), "r"(af[mt][3]),
                          "r"(bfr[nt >> 1][(nt & 1) * 2]), "r"(bfr[nt >> 1][(nt & 1) * 2 + 1]));
                }
        }
    };

    stage(0, 0);
    int s = 0;
    for (int it = 0; it < iters; it++) {
        asm volatile("cp.async.wait_group 0;\n" ::: "memory");
        __syncthreads();
        if (it + 1 < iters) stage(s ^ 1, (it + 1) * BKE);
        compute(s);
        __syncthreads();
        s ^= 1;
    }
}

// ---------------- q/k GEMM: grid (4, 32, 4), z = b*2 + which ------------------
// q output is pre-scaled by 512^-0.5 (folded out of the scores kernel)
__global__ __launch_bounds__(256)
void gemm_qk(const float* __restrict__ qb, const float* __restrict__ kb) {
    const int z = blockIdx.z, b = z >> 1, which = z & 1;
    const int lane = threadIdx.x & 31, w = threadIdx.x >> 5;
    const int wm = (w & 1) * 64, wn = (w >> 1) * 32, gq = lane >> 2, j = lane & 3;
    const float scale = which ? 1.0f : 0.044194173824159216f;   // q gets 512^-0.5
    float acc[4][4][4] = {};

    const bf16* A = g_hn + (size_t)b * NN * CC;
    const bf16* B = which ? g_wk : g_wq;
    bf16* D = (which ? g_k : g_q) + (size_t)b * NN * CC;
    const float* bias = which ? kb : qb;
    const int m0 = blockIdx.y * 128, n0 = blockIdx.x * 128;
    gemm_core(A, CC, B, CC, m0, n0, CC, acc);
    #pragma unroll
    for (int mt = 0; mt < 4; mt++) {
        const int r = m0 + wm + mt * 16 + gq;
        #pragma unroll
        for (int nt = 0; nt < 4; nt++) {
            const int c = n0 + wn + nt * 8 + 2 * j;
            const float b0 = bias[c], b1 = bias[c + 1];
            *(bf162*)&D[(size_t)r * CC + c] =
                __floats2bfloat162_rn((acc[mt][nt][0] + b0) * scale,
                                      (acc[mt][nt][1] + b1) * scale);
            *(bf162*)&D[(size_t)(r + 8) * CC + c] =
                __floats2bfloat162_rn((acc[mt][nt][2] + b0) * scale,
                                      (acc[mt][nt][3] + b1) * scale);
        }
    }
}

// ---------------- scores(+exp+rowsum) and v in ONE launch ----------------------
// grid (1152, 1, 2): idx < 128 -> v tile; else scores tile (q pre-scaled)
__global__ __launch_bounds__(256)
void gemm_scores_v(const float* __restrict__ vb) {
    const int b = blockIdx.z;
    const int idx = blockIdx.x;
    const int lane = threadIdx.x & 31, w = threadIdx.x >> 5;
    const int wm = (w & 1) * 64, wn = (w >> 1) * 32, gq = lane >> 2, j = lane & 3;
    float acc[4][4][4] = {};

    if (idx < 128) {
        // v tile: m = channel (4 tiles), n = token (32 tiles)
        const int m0 = (idx >> 5) * 128, n0 = (idx & 31) * 128;
        bf16* D = g_v + (size_t)b * CC * NN;
        gemm_core(g_wv, CC, g_hn + (size_t)b * NN * CC, CC, m0, n0, CC, acc);
        #pragma unroll
        for (int mt = 0; mt < 4; mt++) {
            const int r = m0 + wm + mt * 16 + gq;
            const float b0 = vb[r], b1 = vb[r + 8];
            #pragma unroll
            for (int nt = 0; nt < 4; nt++) {
                const int c = n0 + wn + nt * 8 + 2 * j;
                *(bf162*)&D[(size_t)r * NN + c] =
                    __floats2bfloat162_rn(acc[mt][nt][0] + b0, acc[mt][nt][1] + b0);
                *(bf162*)&D[(size_t)(r + 8) * NN + c] =
                    __floats2bfloat162_rn(acc[mt][nt][2] + b1, acc[mt][nt][3] + b1);
            }
        }
        return;
    }

    // scores tile
    const int sidx = idx - 128;                  // 0..1023
    const int m0 = (sidx >> 5) * 128, n0 = (sidx & 31) * 128;
    const bf16* A = g_q + (size_t)b * NN * CC;
    const bf16* B = g_k + (size_t)b * NN * CC;
    bf16* __restrict__ P = g_P + (size_t)b * NN * NN;

    __shared__ float srsum[128];
    const int t = threadIdx.x;
    if (t < 128) srsum[t] = 0.f;

    gemm_core(A, CC, B, CC, m0, n0, CC, acc);

    #pragma unroll
    for (int mt = 0; mt < 4; mt++) {
        const int r = wm + mt * 16 + gq;          // local q row
        float s0 = 0.f, s1 = 0.f;
        #pragma unroll
        for (int nt = 0; nt < 4; nt++) {
            const int c = n0 + wn + nt * 8 + 2 * j;
            const float p0 = __expf(acc[mt][nt][0]);
            const float p1 = __expf(acc[mt][nt][1]);
            const float p2 = __expf(acc[mt][nt][2]);
            const float p3 = __expf(acc[mt][nt][3]);
            *(bf162*)&P[(size_t)(m0 + r) * NN + c]     = __floats2bfloat162_rn(p0, p1);
            *(bf162*)&P[(size_t)(m0 + r + 8) * NN + c] = __floats2bfloat162_rn(p2, p3);
            s0 += p0 + p1;
            s1 += p2 + p3;
        }
        s0 += __shfl_xor_sync(~0u, s0, 1); s0 += __shfl_xor_sync(~0u, s0, 2);
        s1 += __shfl_xor_sync(~0u, s1, 1); s1 += __shfl_xor_sync(~0u, s1, 2);
        if (j == 0) {
            atomicAdd(&srsum[r], s0);
            atomicAdd(&srsum[r + 8], s1);
        }
    }
    __syncthreads();
    if (t < 128) atomicAdd(&g_rsum[b * NN + m0 + t], srsum[t]);
}

// ---------------- O = P @ V^T with 1/rowsum normalization ---------------------
__global__ __launch_bounds__(256)
void gemm_out() {
    const int b = blockIdx.z;
    const bf16* A = g_P + (size_t)b * NN * NN;
    const bf16* B = g_v + (size_t)b * CC * NN;
    bf16* D = g_o + (size_t)b * NN * CC;
    const int m0 = blockIdx.y * 128, n0 = blockIdx.x * 128;
    float acc[4][4][4] = {};
    gemm_core(A, NN, B, NN, m0, n0, NN, acc);
    const int lane = threadIdx.x & 31, w = threadIdx.x >> 5;
    const int wm = (w & 1) * 64, wn = (w >> 1) * 32, gq = lane >> 2, j = lane & 3;
    #pragma unroll
    for (int mt = 0; mt < 4; mt++) {
        const int r = m0 + wm + mt * 16 + gq;
        const float inv0 = 1.0f / g_rsum[b * NN + r];
        const float inv1 = 1.0f / g_rsum[b * NN + r + 8];
        #pragma unroll
        for (int nt = 0; nt < 4; nt++) {
            const int c = n0 + wn + nt * 8 + 2 * j;
            *(bf162*)&D[(size_t)r * CC + c] =
                __floats2bfloat162_rn(acc[mt][nt][0] * inv0, acc[mt][nt][1] * inv0);
            *(bf162*)&D[(size_t)(r + 8) * CC + c] =
                __floats2bfloat162_rn(acc[mt][nt][2] * inv1, acc[mt][nt][3] * inv1);
        }
    }
}

// ---------------- proj + bias + residual --------------------------------------
__global__ __launch_bounds__(256)
void gemm_proj(const float* __restrict__ pb, const float* __restrict__ x,
               float* __restrict__ out) {
    const int b = blockIdx.z;
    const bf16* A = g_o + (size_t)b * NN * CC;
    const bf16* B = g_wp;
    const int m0 = blockIdx.y * 128, n0 = blockIdx.x * 128;
    float acc[4][4][4] = {};
    gemm_core(A, CC, B, CC, m0, n0, CC, acc);
    const int lane = threadIdx.x & 31, w = threadIdx.x >> 5;
    const int wm = (w & 1) * 64, wn = (w >> 1) * 32, gq = lane >> 2, j = lane & 3;
    const size_t bofs = (size_t)b * CC * NN;
    #pragma unroll
    for (int mt = 0; mt < 4; mt++) {
        const int r = m0 + wm + mt * 16 + gq;
        #pragma unroll
        for (int nt = 0; nt < 4; nt++) {
            const int c = n0 + wn + nt * 8 + 2 * j;
            const float b0 = pb[c], b1 = pb[c + 1];
            const size_t i00 = bofs + (size_t)c * NN + r;
            const size_t i01 = i00 + NN;
            out[i00]     = acc[mt][nt][0] + b0 + x[i00];
            out[i01]     = acc[mt][nt][1] + b1 + x[i01];
            out[i00 + 8] = acc[mt][nt][2] + b0 + x[i00 + 8];
            out[i01 + 8] = acc[mt][nt][3] + b1 + x[i01 + 8];
        }
    }
}

// ---------------- launch ------------------------------------------------------
extern "C" void kernel_launch(void* const* d_in, const int* in_sizes, int n_in,
                              void* d_out, int out_size) {
    const float* x      = (const float*)d_in[0];
    const float* gn_w   = (const float*)d_in[1];
    const float* gn_b   = (const float*)d_in[2];
    const float* q_w    = (const float*)d_in[3];
    const float* q_b    = (const float*)d_in[4];
    const float* k_w    = (const float*)d_in[5];
    const float* k_b    = (const float*)d_in[6];
    const float* v_w    = (const float*)d_in[7];
    const float* v_b    = (const float*)d_in[8];
    const float* proj_w = (const float*)d_in[9];
    const float* proj_b = (const float*)d_in[10];
    float* out = (float*)d_out;

    cudaFuncSetAttribute(gemm_qk,       cudaFuncAttributeMaxDynamicSharedMemorySize, GC_SMEM);
    cudaFuncSetAttribute(gemm_scores_v, cudaFuncAttributeMaxDynamicSharedMemorySize, GC_SMEM);
    cudaFuncSetAttribute(gemm_out,      cudaFuncAttributeMaxDynamicSharedMemorySize, GC_SMEM);
    cudaFuncSetAttribute(gemm_proj,     cudaFuncAttributeMaxDynamicSharedMemorySize, GC_SMEM);

    prep_kernel<<<1280, 256>>>(q_w, k_w, v_w, proj_w, x);
    gn_apply<<<BB * GRPS * 4, 1024>>>(x, gn_w, gn_b);
    gemm_qk<<<dim3(CC / 128, NN / 128, 2 * BB), 256, GC_SMEM>>>(q_b, k_b);
    gemm_scores_v<<<dim3(1152, 1, BB), 256, GC_SMEM>>>(v_b);
    gemm_out<<<dim3(CC / 128, NN / 128, BB), 256, GC_SMEM>>>();
    gemm_proj<<<dim3(CC / 128, NN / 128, BB), 256, GC_SMEM>>>(proj_b, x, out);
}

// round 15
// speedup vs baseline: 1.0792x; 1.0792x over previous
#include <cuda_runtime.h>
#include <cuda_bf16.h>
#include <cstdint>

#define CC   512
#define NN   4096
#define BB   2
#define GRPS 32
#define CPG  16
#define EPSF 1e-5f
#define BKE  64            // k elements per pipeline stage
#define RSTR 72            // smem row stride in bf16 (64 data + 8 pad), 144B = 16B-aligned
#define GC_SMEM (2 * 2 * 128 * RSTR * 2)   // 73728 bytes (2 stages x A+B tiles)
#define TPITCH 132          // fp32 transpose pitch for proj epilogue

typedef __nv_bfloat16  bf16;
typedef __nv_bfloat162 bf162;

// ---------------- scratch (device globals: allocation-free) ----------------
__device__ bf16  g_hn[BB * NN * CC];            // GN output, token-major [b][n][c]
__device__ bf16  g_q [BB * NN * CC];            // pre-scaled q [b][n][c]
__device__ bf16  g_k [BB * NN * CC];            // [b][n][c]
__device__ bf16  g_v [BB * CC * NN];            // [b][c][n]
__device__ bf16  g_P [BB * (size_t)NN * NN];    // unnormalized exp scores bf16 [b][q][k]
__device__ float g_rsum[BB * NN];               // per-row exp sums
__device__ float g_gstat[BB * GRPS * 2];        // groupnorm partial sums (s, s2)
__device__ bf16  g_o [BB * NN * CC];            // attn out [b][q][c]
__device__ bf16  g_wq[CC * CC], g_wk[CC * CC], g_wv[CC * CC], g_wp[CC * CC];

// ---------------- prep: weight fp32->bf16, zero accs, GN partial stats -------
__global__ __launch_bounds__(256)
void prep_kernel(const float* __restrict__ qw, const float* __restrict__ kw,
                 const float* __restrict__ vw, const float* __restrict__ pw,
                 const float* __restrict__ x) {
    if (blockIdx.x < 1024) {
        const int i = blockIdx.x * 256 + threadIdx.x;
        if (i < BB * NN) g_rsum[i] = 0.f;
        if (i < BB * GRPS * 2) g_gstat[i] = 0.f;
        const int which = i >> 16, j = i & 65535;
        const float* src = which == 0 ? qw : which == 1 ? kw : which == 2 ? vw : pw;
        bf16* dst = which == 0 ? g_wq : which == 1 ? g_wk : which == 2 ? g_wv : g_wp;
        float4 v = ((const float4*)src)[j];
        bf162* d2 = (bf162*)(dst + (size_t)j * 4);
        d2[0] = __floats2bfloat162_rn(v.x, v.y);
        d2[1] = __floats2bfloat162_rn(v.z, v.w);
        return;
    }
    const int idx = blockIdx.x - 1024;           // 0..255
    const int bg = idx >> 2;                     // 0..63
    const int b  = bg / GRPS, g = bg % GRPS;
    const int qy = idx & 3;
    const size_t base = ((size_t)b * CC + (size_t)g * CPG + qy * 4) * NN;
    const float4* __restrict__ xp4 = (const float4*)(x + base);
    const int t = threadIdx.x;
    float s = 0.f, s2 = 0.f;
    #pragma unroll 4
    for (int i = t; i < 4096; i += 256) {
        float4 v = xp4[i];
        s  += v.x + v.y + v.z + v.w;
        s2 += v.x * v.x + v.y * v.y + v.z * v.z + v.w * v.w;
    }
    #pragma unroll
    for (int o = 16; o; o >>= 1) {
        s  += __shfl_xor_sync(~0u, s, o);
        s2 += __shfl_xor_sync(~0u, s2, o);
    }
    __shared__ float r1[8], r2[8];
    const int wid = t >> 5, lid = t & 31;
    if (lid == 0) { r1[wid] = s; r2[wid] = s2; }
    __syncthreads();
    if (t == 0) {
        s = r1[0] + r1[1] + r1[2] + r1[3] + r1[4] + r1[5] + r1[6] + r1[7];
        s2 = r2[0] + r2[1] + r2[2] + r2[3] + r2[4] + r2[5] + r2[6] + r2[7];
        atomicAdd(&g_gstat[bg * 2], s);
        atomicAdd(&g_gstat[bg * 2 + 1], s2);
    }
}

// ---------------- GroupNorm pass 2: apply + transpose to bf16 [n][c] ---------
__global__ __launch_bounds__(1024)
void gn_apply(const float* __restrict__ x,
              const float* __restrict__ gw, const float* __restrict__ gb) {
    const int bg = blockIdx.x >> 2;
    const int b  = bg / GRPS, g = bg % GRPS;
    const int n  = (blockIdx.x & 3) * 1024 + threadIdx.x;
    __shared__ float stat[2];
    if (threadIdx.x < 2) stat[threadIdx.x] = g_gstat[bg * 2 + threadIdx.x];
    __syncthreads();
    const float invN = 1.0f / (float)(CPG * NN);
    const float mean = stat[0] * invN;
    const float var  = stat[1] * invN - mean * mean;
    const float istd = rsqrtf(var + EPSF);

    const float* __restrict__ xs = x + ((size_t)b * CC + (size_t)g * CPG) * NN;
    bf16* __restrict__ dst = g_hn + (size_t)b * NN * CC + g * CPG;
    alignas(16) bf162 o[8];
    #pragma unroll
    for (int ci = 0; ci < CPG; ci += 2) {
        const float sc0 = gw[g * CPG + ci] * istd;
        const float sh0 = gb[g * CPG + ci] - mean * sc0;
        const float sc1 = gw[g * CPG + ci + 1] * istd;
        const float sh1 = gb[g * CPG + ci + 1] - mean * sc1;
        float v0 = xs[(size_t)ci * NN + n] * sc0 + sh0;
        float v1 = xs[(size_t)(ci + 1) * NN + n] * sc1 + sh1;
        o[ci >> 1] = __floats2bfloat162_rn(v0, v1);
    }
    *(uint4*)&dst[(size_t)n * CC]     = *(uint4*)&o[0];
    *(uint4*)&dst[(size_t)n * CC + 8] = *(uint4*)&o[4];
}

// ============================================================================
// bf16 ldmatrix/mma GEMM core — 2-stage, BK=64, block 128x128, warp 64x32
// (exact round-9 measured-best version: two barriers per iteration)
// ============================================================================
__device__ __forceinline__ void gemm_core(
    const bf16* __restrict__ A, int lda,
    const bf16* __restrict__ B, int ldb,
    int m0, int n0, int K, float (&acc)[4][4][4])
{
    extern __shared__ bf16 dsm[];
    bf16* As[2] = { dsm,                  dsm + 2 * 128 * RSTR };
    bf16* Bs[2] = { dsm + 128 * RSTR,     dsm + 3 * 128 * RSTR };
    const int t = threadIdx.x, lane = t & 31, w = t >> 5;
    const int wm = (w & 1) * 64, wn = (w >> 1) * 32;
    const int grp = lane >> 3, lr = lane & 7;

    uint32_t dA[2][4], dB[2][4], asb[2], bsb[2];
    const bf16* gA[4]; const bf16* gB[4];
    #pragma unroll
    for (int l = 0; l < 4; l++) {
        const int i = t + l * 256;
        const int row = i >> 3, c8 = (i & 7) * 8;
        gA[l] = A + (size_t)(m0 + row) * lda + c8;
        gB[l] = B + (size_t)(n0 + row) * ldb + c8;
        #pragma unroll
        for (int s = 0; s < 2; s++) {
            dA[s][l] = (uint32_t)__cvta_generic_to_shared(&As[s][row * RSTR + c8]);
            dB[s][l] = (uint32_t)__cvta_generic_to_shared(&Bs[s][row * RSTR + c8]);
        }
    }
    #pragma unroll
    for (int s = 0; s < 2; s++) {
        asb[s] = (uint32_t)__cvta_generic_to_shared(As[s]);
        bsb[s] = (uint32_t)__cvta_generic_to_shared(Bs[s]);
    }
    int aoff[4], boff[2];
    #pragma unroll
    for (int mt = 0; mt < 4; mt++)
        aoff[mt] = ((wm + mt * 16 + (grp & 1) * 8 + lr) * RSTR + (grp >> 1) * 8) * 2;
    #pragma unroll
    for (int bt = 0; bt < 2; bt++)
        boff[bt] = ((wn + bt * 16 + (grp >> 1) * 8 + lr) * RSTR + (grp & 1) * 8) * 2;

    const int iters = K / BKE;

    auto stage = [&](int s, int kc) {
        #pragma unroll
        for (int l = 0; l < 4; l++) {
            asm volatile("cp.async.cg.shared.global [%0], [%1], 16;\n" :: "r"(dA[s][l]), "l"(gA[l] + kc) : "memory");
            asm volatile("cp.async.cg.shared.global [%0], [%1], 16;\n" :: "r"(dB[s][l]), "l"(gB[l] + kc) : "memory");
        }
        asm volatile("cp.async.commit_group;\n" ::: "memory");
    };
    auto compute = [&](int s) {
        #pragma unroll
        for (int kk = 0; kk < 4; kk++) {
            uint32_t af[4][4], bfr[2][4];
            #pragma unroll
            for (int mt = 0; mt < 4; mt++) {
                asm volatile("ldmatrix.sync.aligned.m8n8.x4.shared.b16 {%0,%1,%2,%3}, [%4];\n"
                             : "=r"(af[mt][0]), "=r"(af[mt][1]), "=r"(af[mt][2]), "=r"(af[mt][3])
                             : "r"(asb[s] + aoff[mt] + kk * 32));
            }
            #pragma unroll
            for (int bt = 0; bt < 2; bt++) {
                asm volatile("ldmatrix.sync.aligned.m8n8.x4.shared.b16 {%0,%1,%2,%3}, [%4];\n"
                             : "=r"(bfr[bt][0]), "=r"(bfr[bt][1]), "=r"(bfr[bt][2]), "=r"(bfr[bt][3])
                             : "r"(bsb[s] + boff[bt] + kk * 32));
            }
            #pragma unroll
            for (int mt = 0; mt < 4; mt++)
                #pragma unroll
                for (int nt = 0; nt < 4; nt++) {
                    asm volatile(
                        "mma.sync.aligned.m16n8k16.row.col.f32.bf16.bf16.f32 "
                        "{%0,%1,%2,%3},{%4,%5,%6,%7},{%8,%9},{%0,%1,%2,%3};\n"
                        : "+f"(acc[mt][nt][0]), "+f"(acc[mt][nt][1]),
                          "+f"(acc[mt][nt][2]), "+f"(acc[mt][nt][3])
                        : "r"(af[mt][0]), "r"(af[mt][1]), "r"(af[mt][2]), "r"(af[mt][3]),
                          "r"(bfr[nt >> 1][(nt & 1) * 2]), "r"(bfr[nt >> 1][(nt & 1) * 2 + 1]));
                }
        }
    };

    stage(0, 0);
    int s = 0;
    for (int it = 0; it < iters; it++) {
        asm volatile("cp.async.wait_group 0;\n" ::: "memory");
        __syncthreads();
        if (it + 1 < iters) stage(s ^ 1, (it + 1) * BKE);
        compute(s);
        __syncthreads();
        s ^= 1;
    }
}

// ---------------- fused QKV: grid (4, 32, 6), z = b*3 + which -----------------
// q output is pre-scaled by 512^-0.5 (folded out of the scores kernel)
__global__ __launch_bounds__(256, 2)
void gemm_qkv(const float* __restrict__ qb, const float* __restrict__ kb,
              const float* __restrict__ vb) {
    const int z = blockIdx.z, b = z / 3, which = z % 3;
    const int lane = threadIdx.x & 31, w = threadIdx.x >> 5;
    const int wm = (w & 1) * 64, wn = (w >> 1) * 32, gq = lane >> 2, j = lane & 3;
    float acc[4][4][4] = {};

    if (which < 2) {
        const bf16* A = g_hn + (size_t)b * NN * CC;
        const bf16* B = which ? g_wk : g_wq;
        bf16* D = (which ? g_k : g_q) + (size_t)b * NN * CC;
        const float* bias = which ? kb : qb;
        const float scale = which ? 1.0f : 0.044194173824159216f;
        const int m0 = blockIdx.y * 128, n0 = blockIdx.x * 128;
        gemm_core(A, CC, B, CC, m0, n0, CC, acc);
        #pragma unroll
        for (int mt = 0; mt < 4; mt++) {
            const int r = m0 + wm + mt * 16 + gq;
            #pragma unroll
            for (int nt = 0; nt < 4; nt++) {
                const int c = n0 + wn + nt * 8 + 2 * j;
                const float b0 = bias[c], b1 = bias[c + 1];
                *(bf162*)&D[(size_t)r * CC + c] =
                    __floats2bfloat162_rn((acc[mt][nt][0] + b0) * scale,
                                          (acc[mt][nt][1] + b1) * scale);
                *(bf162*)&D[(size_t)(r + 8) * CC + c] =
                    __floats2bfloat162_rn((acc[mt][nt][2] + b0) * scale,
                                          (acc[mt][nt][3] + b1) * scale);
            }
        }
    } else {
        const int m0 = blockIdx.x * 128, n0 = blockIdx.y * 128;   // m = c, n = token
        bf16* D = g_v + (size_t)b * CC * NN;
        gemm_core(g_wv, CC, g_hn + (size_t)b * NN * CC, CC, m0, n0, CC, acc);
        #pragma unroll
        for (int mt = 0; mt < 4; mt++) {
            const int r = m0 + wm + mt * 16 + gq;
            const float b0 = vb[r], b1 = vb[r + 8];
            #pragma unroll
            for (int nt = 0; nt < 4; nt++) {
                const int c = n0 + wn + nt * 8 + 2 * j;
                *(bf162*)&D[(size_t)r * NN + c] =
                    __floats2bfloat162_rn(acc[mt][nt][0] + b0, acc[mt][nt][1] + b0);
                *(bf162*)&D[(size_t)(r + 8) * NN + c] =
                    __floats2bfloat162_rn(acc[mt][nt][2] + b1, acc[mt][nt][3] + b1);
            }
        }
    }
}

// ---------------- fused scores + exp + rowsum: grid (32, 32, 2) ---------------
__global__ __launch_bounds__(256, 2)
void gemm_scores_exp() {
    const int b  = blockIdx.z;
    const int m0 = blockIdx.y * 128, n0 = blockIdx.x * 128;
    const bf16* A = g_q + (size_t)b * NN * CC;
    const bf16* B = g_k + (size_t)b * NN * CC;
    bf16* __restrict__ P = g_P + (size_t)b * NN * NN;

    __shared__ float srsum[128];
    const int t = threadIdx.x;
    if (t < 128) srsum[t] = 0.f;

    float acc[4][4][4] = {};
    gemm_core(A, CC, B, CC, m0, n0, CC, acc);

    const int lane = t & 31, w = t >> 5;
    const int wm = (w & 1) * 64, wn = (w >> 1) * 32, gq = lane >> 2, j = lane & 3;
    #pragma unroll
    for (int mt = 0; mt < 4; mt++) {
        const int r = wm + mt * 16 + gq;          // local q row
        float s0 = 0.f, s1 = 0.f;
        #pragma unroll
        for (int nt = 0; nt < 4; nt++) {
            const int c = n0 + wn + nt * 8 + 2 * j;
            const float p0 = __expf(acc[mt][nt][0]);
            const float p1 = __expf(acc[mt][nt][1]);
            const float p2 = __expf(acc[mt][nt][2]);
            const float p3 = __expf(acc[mt][nt][3]);
            *(bf162*)&P[(size_t)(m0 + r) * NN + c]     = __floats2bfloat162_rn(p0, p1);
            *(bf162*)&P[(size_t)(m0 + r + 8) * NN + c] = __floats2bfloat162_rn(p2, p3);
            s0 += p0 + p1;
            s1 += p2 + p3;
        }
        s0 += __shfl_xor_sync(~0u, s0, 1); s0 += __shfl_xor_sync(~0u, s0, 2);
        s1 += __shfl_xor_sync(~0u, s1, 1); s1 += __shfl_xor_sync(~0u, s1, 2);
        if (j == 0) {
            atomicAdd(&srsum[r], s0);
            atomicAdd(&srsum[r + 8], s1);
        }
    }
    __syncthreads();
    if (t < 128) atomicAdd(&g_rsum[b * NN + m0 + t], srsum[t]);
}

// ---------------- O = P @ V^T with 1/rowsum normalization ---------------------
__global__ __launch_bounds__(256, 2)
void gemm_out() {
    const int b = blockIdx.z;
    const bf16* A = g_P + (size_t)b * NN * NN;
    const bf16* B = g_v + (size_t)b * CC * NN;
    bf16* D = g_o + (size_t)b * NN * CC;
    const int m0 = blockIdx.y * 128, n0 = blockIdx.x * 128;
    float acc[4][4][4] = {};
    gemm_core(A, NN, B, NN, m0, n0, NN, acc);
    const int lane = threadIdx.x & 31, w = threadIdx.x >> 5;
    const int wm = (w & 1) * 64, wn = (w >> 1) * 32, gq = lane >> 2, j = lane & 3;
    #pragma unroll
    for (int mt = 0; mt < 4; mt++) {
        const int r = m0 + wm + mt * 16 + gq;
        const float inv0 = 1.0f / g_rsum[b * NN + r];
        const float inv1 = 1.0f / g_rsum[b * NN + r + 8];
        #pragma unroll
        for (int nt = 0; nt < 4; nt++) {
            const int c = n0 + wn + nt * 8 + 2 * j;
            *(bf162*)&D[(size_t)r * CC + c] =
                __floats2bfloat162_rn(acc[mt][nt][0] * inv0, acc[mt][nt][1] * inv0);
            *(bf162*)&D[(size_t)(r + 8) * CC + c] =
                __floats2bfloat162_rn(acc[mt][nt][2] * inv1, acc[mt][nt][3] * inv1);
        }
    }
}

// ---------------- proj + bias + residual, smem-transposed coalesced epilogue --
__global__ __launch_bounds__(256, 2)
void gemm_proj(const float* __restrict__ pb, const float* __restrict__ x,
               float* __restrict__ out) {
    const int b = blockIdx.z;
    const bf16* A = g_o + (size_t)b * NN * CC;
    const bf16* B = g_wp;
    const int m0 = blockIdx.y * 128, n0 = blockIdx.x * 128;   // m = token, n = c_out
    float acc[4][4][4] = {};
    gemm_core(A, CC, B, CC, m0, n0, CC, acc);

    // transpose acc through smem: S[c_local][token_local], pitch TPITCH
    extern __shared__ bf16 dsm[];
    float* S = (float*)dsm;
    const int t = threadIdx.x, lane = t & 31, w = t >> 5;
    const int wm = (w & 1) * 64, wn = (w >> 1) * 32, gq = lane >> 2, j = lane & 3;
    #pragma unroll
    for (int mt = 0; mt < 4; mt++) {
        const int r = wm + mt * 16 + gq;        // token_local
        #pragma unroll
        for (int nt = 0; nt < 4; nt++) {
            const int c = wn + nt * 8 + 2 * j;  // c_local
            S[(c)     * TPITCH + r]     = acc[mt][nt][0];
            S[(c + 1) * TPITCH + r]     = acc[mt][nt][1];
            S[(c)     * TPITCH + r + 8] = acc[mt][nt][2];
            S[(c + 1) * TPITCH + r + 8] = acc[mt][nt][3];
        }
    }
    __syncthreads();

    const size_t bofs = (size_t)b * CC * NN;
    for (int i = t; i < 128 * 32; i += 256) {
        const int row = i >> 5, c4 = (i & 31) * 4;
        const float bias = pb[n0 + row];
        const size_t gidx = bofs + (size_t)(n0 + row) * NN + m0 + c4;
        const float4 xv = *(const float4*)&x[gidx];
        const float* sp = &S[row * TPITCH + c4];
        float4 r4 = make_float4(sp[0] + bias + xv.x, sp[1] + bias + xv.y,
                                sp[2] + bias + xv.z, sp[3] + bias + xv.w);
        *(float4*)&out[gidx] = r4;
    }
}

// ---------------- launch ------------------------------------------------------
extern "C" void kernel_launch(void* const* d_in, const int* in_sizes, int n_in,
                              void* d_out, int out_size) {
    const float* x      = (const float*)d_in[0];
    const float* gn_w   = (const float*)d_in[1];
    const float* gn_b   = (const float*)d_in[2];
    const float* q_w    = (const float*)d_in[3];
    const float* q_b    = (const float*)d_in[4];
    const float* k_w    = (const float*)d_in[5];
    const float* k_b    = (const float*)d_in[6];
    const float* v_w    = (const float*)d_in[7];
    const float* v_b    = (const float*)d_in[8];
    const float* proj_w = (const float*)d_in[9];
    const float* proj_b = (const float*)d_in[10];
    float* out = (float*)d_out;

    cudaFuncSetAttribute(gemm_qkv,        cudaFuncAttributeMaxDynamicSharedMemorySize, GC_SMEM);
    cudaFuncSetAttribute(gemm_scores_exp, cudaFuncAttributeMaxDynamicSharedMemorySize, GC_SMEM);
    cudaFuncSetAttribute(gemm_out,        cudaFuncAttributeMaxDynamicSharedMemorySize, GC_SMEM);
    cudaFuncSetAttribute(gemm_proj,       cudaFuncAttributeMaxDynamicSharedMemorySize, GC_SMEM);

    prep_kernel<<<1280, 256>>>(q_w, k_w, v_w, proj_w, x);
    gn_apply<<<BB * GRPS * 4, 1024>>>(x, gn_w, gn_b);
    gemm_qkv<<<dim3(CC / 128, NN / 128, 3 * BB), 256, GC_SMEM>>>(q_b, k_b, v_b);
    gemm_scores_exp<<<dim3(NN / 128, NN / 128, BB), 256, GC_SMEM>>>();
    gemm_out<<<dim3(CC / 128, NN / 128, BB), 256, GC_SMEM>>>();
    gemm_proj<<<dim3(CC / 128, NN / 128, BB), 256, GC_SMEM>>>(proj_b, x, out);
}

// round 16
// speedup vs baseline: 1.0861x; 1.0064x over previous
#include <cuda_runtime.h>
#include <cuda_bf16.h>
#include <cstdint>

#define CC   512
#define NN   4096
#define BB   2
#define GRPS 32
#define CPG  16
#define EPSF 1e-5f
#define BKE  64            // k elements per pipeline stage
#define RSTR 72            // smem row stride in bf16 (64 data + 8 pad), 144B = 16B-aligned
#define GC_SMEM (2 * 2 * 128 * RSTR * 2)   // 73728 bytes (2 stages x A+B tiles)
#define TPITCH 132          // fp32 transpose pitch for proj epilogue

typedef __nv_bfloat16  bf16;
typedef __nv_bfloat162 bf162;

// ---------------- scratch (device globals: allocation-free) ----------------
__device__ bf16  g_hn[BB * NN * CC];            // GN output, token-major [b][n][c]
__device__ bf16  g_q [BB * NN * CC];            // [b][n][c]
__device__ bf16  g_k [BB * NN * CC];            // [b][n][c]
__device__ bf16  g_v [BB * CC * NN];            // [b][c][n]
__device__ bf16  g_P [BB * (size_t)NN * NN];    // unnormalized exp scores bf16 [b][q][k]
__device__ float g_rsum[BB * NN];               // per-row exp sums
__device__ float g_gstat[BB * GRPS * 2];        // groupnorm partial sums (s, s2)
__device__ bf16  g_o [BB * NN * CC];            // UNNORMALIZED attn out [b][q][c]
__device__ bf16  g_wq[CC * CC], g_wk[CC * CC], g_wv[CC * CC], g_wp[CC * CC];

// ---------------- prep: weight fp32->bf16, zero accs, GN partial stats -------
__global__ __launch_bounds__(256)
void prep_kernel(const float* __restrict__ qw, const float* __restrict__ kw,
                 const float* __restrict__ vw, const float* __restrict__ pw,
                 const float* __restrict__ x) {
    if (blockIdx.x < 1024) {
        const int i = blockIdx.x * 256 + threadIdx.x;
        if (i < BB * NN) g_rsum[i] = 0.f;
        if (i < BB * GRPS * 2) g_gstat[i] = 0.f;
        const int which = i >> 16, j = i & 65535;
        const float* src = which == 0 ? qw : which == 1 ? kw : which == 2 ? vw : pw;
        bf16* dst = which == 0 ? g_wq : which == 1 ? g_wk : which == 2 ? g_wv : g_wp;
        float4 v = ((const float4*)src)[j];
        bf162* d2 = (bf162*)(dst + (size_t)j * 4);
        d2[0] = __floats2bfloat162_rn(v.x, v.y);
        d2[1] = __floats2bfloat162_rn(v.z, v.w);
        return;
    }
    const int idx = blockIdx.x - 1024;           // 0..255
    const int bg = idx >> 2;                     // 0..63
    const int b  = bg / GRPS, g = bg % GRPS;
    const int qy = idx & 3;
    const size_t base = ((size_t)b * CC + (size_t)g * CPG + qy * 4) * NN;
    const float4* __restrict__ xp4 = (const float4*)(x + base);
    const int t = threadIdx.x;
    float s = 0.f, s2 = 0.f;
    #pragma unroll 4
    for (int i = t; i < 4096; i += 256) {
        float4 v = xp4[i];
        s  += v.x + v.y + v.z + v.w;
        s2 += v.x * v.x + v.y * v.y + v.z * v.z + v.w * v.w;
    }
    #pragma unroll
    for (int o = 16; o; o >>= 1) {
        s  += __shfl_xor_sync(~0u, s, o);
        s2 += __shfl_xor_sync(~0u, s2, o);
    }
    __shared__ float r1[8], r2[8];
    const int wid = t >> 5, lid = t & 31;
    if (lid == 0) { r1[wid] = s; r2[wid] = s2; }
    __syncthreads();
    if (t == 0) {
        s = r1[0] + r1[1] + r1[2] + r1[3] + r1[4] + r1[5] + r1[6] + r1[7];
        s2 = r2[0] + r2[1] + r2[2] + r2[3] + r2[4] + r2[5] + r2[6] + r2[7];
        atomicAdd(&g_gstat[bg * 2], s);
        atomicAdd(&g_gstat[bg * 2 + 1], s2);
    }
}

// ---------------- GroupNorm pass 2: apply + transpose to bf16 [n][c] ---------
__global__ __launch_bounds__(1024)
void gn_apply(const float* __restrict__ x,
              const float* __restrict__ gw, const float* __restrict__ gb) {
    const int bg = blockIdx.x >> 2;
    const int b  = bg / GRPS, g = bg % GRPS;
    const int n  = (blockIdx.x & 3) * 1024 + threadIdx.x;
    __shared__ float stat[2];
    if (threadIdx.x < 2) stat[threadIdx.x] = g_gstat[bg * 2 + threadIdx.x];
    __syncthreads();
    const float invN = 1.0f / (float)(CPG * NN);
    const float mean = stat[0] * invN;
    const float var  = stat[1] * invN - mean * mean;
    const float istd = rsqrtf(var + EPSF);

    const float* __restrict__ xs = x + ((size_t)b * CC + (size_t)g * CPG) * NN;
    bf16* __restrict__ dst = g_hn + (size_t)b * NN * CC + g * CPG;
    alignas(16) bf162 o[8];
    #pragma unroll
    for (int ci = 0; ci < CPG; ci += 2) {
        const float sc0 = gw[g * CPG + ci] * istd;
        const float sh0 = gb[g * CPG + ci] - mean * sc0;
        const float sc1 = gw[g * CPG + ci + 1] * istd;
        const float sh1 = gb[g * CPG + ci + 1] - mean * sc1;
        float v0 = xs[(size_t)ci * NN + n] * sc0 + sh0;
        float v1 = xs[(size_t)(ci + 1) * NN + n] * sc1 + sh1;
        o[ci >> 1] = __floats2bfloat162_rn(v0, v1);
    }
    *(uint4*)&dst[(size_t)n * CC]     = *(uint4*)&o[0];
    *(uint4*)&dst[(size_t)n * CC + 8] = *(uint4*)&o[4];
}

// ============================================================================
// bf16 ldmatrix/mma GEMM core — 2-stage, BK=64, block 128x128, warp 64x32
// (exact round-9 measured-best version: two barriers per iteration)
// ============================================================================
__device__ __forceinline__ void gemm_core(
    const bf16* __restrict__ A, int lda,
    const bf16* __restrict__ B, int ldb,
    int m0, int n0, int K, float (&acc)[4][4][4])
{
    extern __shared__ bf16 dsm[];
    bf16* As[2] = { dsm,                  dsm + 2 * 128 * RSTR };
    bf16* Bs[2] = { dsm + 128 * RSTR,     dsm + 3 * 128 * RSTR };
    const int t = threadIdx.x, lane = t & 31, w = t >> 5;
    const int wm = (w & 1) * 64, wn = (w >> 1) * 32;
    const int grp = lane >> 3, lr = lane & 7;

    uint32_t dA[2][4], dB[2][4], asb[2], bsb[2];
    const bf16* gA[4]; const bf16* gB[4];
    #pragma unroll
    for (int l = 0; l < 4; l++) {
        const int i = t + l * 256;
        const int row = i >> 3, c8 = (i & 7) * 8;
        gA[l] = A + (size_t)(m0 + row) * lda + c8;
        gB[l] = B + (size_t)(n0 + row) * ldb + c8;
        #pragma unroll
        for (int s = 0; s < 2; s++) {
            dA[s][l] = (uint32_t)__cvta_generic_to_shared(&As[s][row * RSTR + c8]);
            dB[s][l] = (uint32_t)__cvta_generic_to_shared(&Bs[s][row * RSTR + c8]);
        }
    }
    #pragma unroll
    for (int s = 0; s < 2; s++) {
        asb[s] = (uint32_t)__cvta_generic_to_shared(As[s]);
        bsb[s] = (uint32_t)__cvta_generic_to_shared(Bs[s]);
    }
    int aoff[4], boff[2];
    #pragma unroll
    for (int mt = 0; mt < 4; mt++)
        aoff[mt] = ((wm + mt * 16 + (grp & 1) * 8 + lr) * RSTR + (grp >> 1) * 8) * 2;
    #pragma unroll
    for (int bt = 0; bt < 2; bt++)
        boff[bt] = ((wn + bt * 16 + (grp >> 1) * 8 + lr) * RSTR + (grp & 1) * 8) * 2;

    const int iters = K / BKE;

    auto stage = [&](int s, int kc) {
        #pragma unroll
        for (int l = 0; l < 4; l++) {
            asm volatile("cp.async.cg.shared.global [%0], [%1], 16;\n" :: "r"(dA[s][l]), "l"(gA[l] + kc) : "memory");
            asm volatile("cp.async.cg.shared.global [%0], [%1], 16;\n" :: "r"(dB[s][l]), "l"(gB[l] + kc) : "memory");
        }
        asm volatile("cp.async.commit_group;\n" ::: "memory");
    };
    auto compute = [&](int s) {
        #pragma unroll
        for (int kk = 0; kk < 4; kk++) {
            uint32_t af[4][4], bfr[2][4];
            #pragma unroll
            for (int mt = 0; mt < 4; mt++) {
                asm volatile("ldmatrix.sync.aligned.m8n8.x4.shared.b16 {%0,%1,%2,%3}, [%4];\n"
                             : "=r"(af[mt][0]), "=r"(af[mt][1]), "=r"(af[mt][2]), "=r"(af[mt][3])
                             : "r"(asb[s] + aoff[mt] + kk * 32));
            }
            #pragma unroll
            for (int bt = 0; bt < 2; bt++) {
                asm volatile("ldmatrix.sync.aligned.m8n8.x4.shared.b16 {%0,%1,%2,%3}, [%4];\n"
                             : "=r"(bfr[bt][0]), "=r"(bfr[bt][1]), "=r"(bfr[bt][2]), "=r"(bfr[bt][3])
                             : "r"(bsb[s] + boff[bt] + kk * 32));
            }
            #pragma unroll
            for (int mt = 0; mt < 4; mt++)
                #pragma unroll
                for (int nt = 0; nt < 4; nt++) {
                    asm volatile(
                        "mma.sync.aligned.m16n8k16.row.col.f32.bf16.bf16.f32 "
                        "{%0,%1,%2,%3},{%4,%5,%6,%7},{%8,%9},{%0,%1,%2,%3};\n"
                        : "+f"(acc[mt][nt][0]), "+f"(acc[mt][nt][1]),
                          "+f"(acc[mt][nt][2]), "+f"(acc[mt][nt][3])
                        : "r"(af[mt][0]), "r"(af[mt][1]), "r"(af[mt][2]), "r"(af[mt][3]),
                          "r"(bfr[nt >> 1][(nt & 1) * 2]), "r"(bfr[nt >> 1][(nt & 1) * 2 + 1]));
                }
        }
    };

    stage(0, 0);
    int s = 0;
    for (int it = 0; it < iters; it++) {
        asm volatile("cp.async.wait_group 0;\n" ::: "memory");
        __syncthreads();
        if (it + 1 < iters) stage(s ^ 1, (it + 1) * BKE);
        compute(s);
        __syncthreads();
        s ^= 1;
    }
}

// ---------------- fused QKV: grid (4, 32, 6), z = b*3 + which -----------------
__global__ __launch_bounds__(256)
void gemm_qkv(const float* __restrict__ qb, const float* __restrict__ kb,
              const float* __restrict__ vb) {
    const int z = blockIdx.z, b = z / 3, which = z % 3;
    const int lane = threadIdx.x & 31, w = threadIdx.x >> 5;
    const int wm = (w & 1) * 64, wn = (w >> 1) * 32, gq = lane >> 2, j = lane & 3;
    float acc[4][4][4] = {};

    if (which < 2) {
        const bf16* A = g_hn + (size_t)b * NN * CC;
        const bf16* B = which ? g_wk : g_wq;
        bf16* D = (which ? g_k : g_q) + (size_t)b * NN * CC;
        const float* bias = which ? kb : qb;
        const int m0 = blockIdx.y * 128, n0 = blockIdx.x * 128;
        gemm_core(A, CC, B, CC, m0, n0, CC, acc);
        #pragma unroll
        for (int mt = 0; mt < 4; mt++) {
            const int r = m0 + wm + mt * 16 + gq;
            #pragma unroll
            for (int nt = 0; nt < 4; nt++) {
                const int c = n0 + wn + nt * 8 + 2 * j;
                const float b0 = bias[c], b1 = bias[c + 1];
                *(bf162*)&D[(size_t)r * CC + c] =
                    __floats2bfloat162_rn(acc[mt][nt][0] + b0, acc[mt][nt][1] + b1);
                *(bf162*)&D[(size_t)(r + 8) * CC + c] =
                    __floats2bfloat162_rn(acc[mt][nt][2] + b0, acc[mt][nt][3] + b1);
            }
        }
    } else {
        const int m0 = blockIdx.x * 128, n0 = blockIdx.y * 128;   // m = c, n = token
        bf16* D = g_v + (size_t)b * CC * NN;
        gemm_core(g_wv, CC, g_hn + (size_t)b * NN * CC, CC, m0, n0, CC, acc);
        #pragma unroll
        for (int mt = 0; mt < 4; mt++) {
            const int r = m0 + wm + mt * 16 + gq;
            const float b0 = vb[r], b1 = vb[r + 8];
            #pragma unroll
            for (int nt = 0; nt < 4; nt++) {
                const int c = n0 + wn + nt * 8 + 2 * j;
                *(bf162*)&D[(size_t)r * NN + c] =
                    __floats2bfloat162_rn(acc[mt][nt][0] + b0, acc[mt][nt][1] + b0);
                *(bf162*)&D[(size_t)(r + 8) * NN + c] =
                    __floats2bfloat162_rn(acc[mt][nt][2] + b1, acc[mt][nt][3] + b1);
            }
        }
    }
}

// ---------------- fused scores + exp + rowsum: grid (32, 32, 2) ---------------
__global__ __launch_bounds__(256)
void gemm_scores_exp(float scale) {
    const int b  = blockIdx.z;
    const int m0 = blockIdx.y * 128, n0 = blockIdx.x * 128;
    const bf16* A = g_q + (size_t)b * NN * CC;
    const bf16* B = g_k + (size_t)b * NN * CC;
    bf16* __restrict__ P = g_P + (size_t)b * NN * NN;

    __shared__ float srsum[128];
    const int t = threadIdx.x;
    if (t < 128) srsum[t] = 0.f;

    float acc[4][4][4] = {};
    gemm_core(A, CC, B, CC, m0, n0, CC, acc);

    const int lane = t & 31, w = t >> 5;
    const int wm = (w & 1) * 64, wn = (w >> 1) * 32, gq = lane >> 2, j = lane & 3;
    #pragma unroll
    for (int mt = 0; mt < 4; mt++) {
        const int r = wm + mt * 16 + gq;          // local q row
        float s0 = 0.f, s1 = 0.f;
        #pragma unroll
        for (int nt = 0; nt < 4; nt++) {
            const int c = n0 + wn + nt * 8 + 2 * j;
            const float p0 = __expf(acc[mt][nt][0] * scale);
            const float p1 = __expf(acc[mt][nt][1] * scale);
            const float p2 = __expf(acc[mt][nt][2] * scale);
            const float p3 = __expf(acc[mt][nt][3] * scale);
            *(bf162*)&P[(size_t)(m0 + r) * NN + c]     = __floats2bfloat162_rn(p0, p1);
            *(bf162*)&P[(size_t)(m0 + r + 8) * NN + c] = __floats2bfloat162_rn(p2, p3);
            s0 += p0 + p1;
            s1 += p2 + p3;
        }
        s0 += __shfl_xor_sync(~0u, s0, 1); s0 += __shfl_xor_sync(~0u, s0, 2);
        s1 += __shfl_xor_sync(~0u, s1, 1); s1 += __shfl_xor_sync(~0u, s1, 2);
        if (j == 0) {
            atomicAdd(&srsum[r], s0);
            atomicAdd(&srsum[r + 8], s1);
        }
    }
    __syncthreads();
    if (t < 128) atomicAdd(&g_rsum[b * NN + m0 + t], srsum[t]);
}

// ---------------- O = P @ V^T (UNNORMALIZED — 1/rowsum deferred to proj) ------
__global__ __launch_bounds__(256)
void gemm_out() {
    const int b = blockIdx.z;
    const bf16* A = g_P + (size_t)b * NN * NN;
    const bf16* B = g_v + (size_t)b * CC * NN;
    bf16* D = g_o + (size_t)b * NN * CC;
    const int m0 = blockIdx.y * 128, n0 = blockIdx.x * 128;
    float acc[4][4][4] = {};
    gemm_core(A, NN, B, NN, m0, n0, NN, acc);
    const int lane = threadIdx.x & 31, w = threadIdx.x >> 5;
    const int wm = (w & 1) * 64, wn = (w >> 1) * 32, gq = lane >> 2, j = lane & 3;
    #pragma unroll
    for (int mt = 0; mt < 4; mt++) {
        const int r = m0 + wm + mt * 16 + gq;
        #pragma unroll
        for (int nt = 0; nt < 4; nt++) {
            const int c = n0 + wn + nt * 8 + 2 * j;
            *(bf162*)&D[(size_t)r * CC + c] =
                __floats2bfloat162_rn(acc[mt][nt][0], acc[mt][nt][1]);
            *(bf162*)&D[(size_t)(r + 8) * CC + c] =
                __floats2bfloat162_rn(acc[mt][nt][2], acc[mt][nt][3]);
        }
    }
}

// ---------------- proj + deferred 1/rsum + bias + residual (transposed) -------
__global__ __launch_bounds__(256)
void gemm_proj(const float* __restrict__ pb, const float* __restrict__ x,
               float* __restrict__ out) {
    const int b = blockIdx.z;
    const bf16* A = g_o + (size_t)b * NN * CC;
    const bf16* B = g_wp;
    const int m0 = blockIdx.y * 128, n0 = blockIdx.x * 128;   // m = token, n = c_out
    float acc[4][4][4] = {};
    gemm_core(A, CC, B, CC, m0, n0, CC, acc);

    // transpose acc through smem: S[c_local][token_local], pitch TPITCH
    extern __shared__ bf16 dsm[];
    float* S = (float*)dsm;
    const int t = threadIdx.x, lane = t & 31, w = t >> 5;
    const int wm = (w & 1) * 64, wn = (w >> 1) * 32, gq = lane >> 2, j = lane & 3;
    #pragma unroll
    for (int mt = 0; mt < 4; mt++) {
        const int r = wm + mt * 16 + gq;        // token_local
        #pragma unroll
        for (int nt = 0; nt < 4; nt++) {
            const int c = wn + nt * 8 + 2 * j;  // c_local
            S[(c)     * TPITCH + r]     = acc[mt][nt][0];
            S[(c + 1) * TPITCH + r]     = acc[mt][nt][1];
            S[(c)     * TPITCH + r + 8] = acc[mt][nt][2];
            S[(c + 1) * TPITCH + r + 8] = acc[mt][nt][3];
        }
    }
    __syncthreads();

    // coalesced sweep with deferred normalization: out = S*inv[token] + pb + x
    const size_t bofs = (size_t)b * CC * NN;
    const float* __restrict__ rs = g_rsum + b * NN + m0;
    for (int i = t; i < 128 * 32; i += 256) {
        const int row = i >> 5, c4 = (i & 31) * 4;      // row = c_out, c4 = token_local
        const float bias = pb[n0 + row];
        const float4 rsv = *(const float4*)&rs[c4];
        const size_t gidx = bofs + (size_t)(n0 + row) * NN + m0 + c4;
        const float4 xv = *(const float4*)&x[gidx];
        const float* sp = &S[row * TPITCH + c4];
        float4 r4 = make_float4(sp[0] / rsv.x + bias + xv.x,
                                sp[1] / rsv.y + bias + xv.y,
                                sp[2] / rsv.z + bias + xv.z,
                                sp[3] / rsv.w + bias + xv.w);
        *(float4*)&out[gidx] = r4;
    }
}

// ---------------- launch ------------------------------------------------------
extern "C" void kernel_launch(void* const* d_in, const int* in_sizes, int n_in,
                              void* d_out, int out_size) {
    const float* x      = (const float*)d_in[0];
    const float* gn_w   = (const float*)d_in[1];
    const float* gn_b   = (const float*)d_in[2];
    const float* q_w    = (const float*)d_in[3];
    const float* q_b    = (const float*)d_in[4];
    const float* k_w    = (const float*)d_in[5];
    const float* k_b    = (const float*)d_in[6];
    const float* v_w    = (const float*)d_in[7];
    const float* v_b    = (const float*)d_in[8];
    const float* proj_w = (const float*)d_in[9];
    const float* proj_b = (const float*)d_in[10];
    float* out = (float*)d_out;

    cudaFuncSetAttribute(gemm_qkv,        cudaFuncAttributeMaxDynamicSharedMemorySize, GC_SMEM);
    cudaFuncSetAttribute(gemm_scores_exp, cudaFuncAttributeMaxDynamicSharedMemorySize, GC_SMEM);
    cudaFuncSetAttribute(gemm_out,        cudaFuncAttributeMaxDynamicSharedMemorySize, GC_SMEM);
    cudaFuncSetAttribute(gemm_proj,       cudaFuncAttributeMaxDynamicSharedMemorySize, GC_SMEM);

    prep_kernel<<<1280, 256>>>(q_w, k_w, v_w, proj_w, x);
    gn_apply<<<BB * GRPS * 4, 1024>>>(x, gn_w, gn_b);
    gemm_qkv<<<dim3(CC / 128, NN / 128, 3 * BB), 256, GC_SMEM>>>(q_b, k_b, v_b);
    const float scale = 0.044194173824159216f;   // 512^-0.5
    gemm_scores_exp<<<dim3(NN / 128, NN / 128, BB), 256, GC_SMEM>>>(scale);
    gemm_out<<<dim3(CC / 128, NN / 128, BB), 256, GC_SMEM>>>();
    gemm_proj<<<dim3(CC / 128, NN / 128, BB), 256, GC_SMEM>>>(proj_b, x, out);
}